// round 16
// baseline (speedup 1.0000x reference)
#include <cuda_runtime.h>
#include <cuda_bf16.h>
#include <cstdint>

// Problem constants
#define S_LEN 2048
#define BATCH 2
#define HEADS 16
#define HD    64
#define DM    1024
#define BH    (BATCH*HEADS)     // 32
#define MROWS (BATCH*S_LEN)     // 4096
#define SCALE 0.125f            // 1/sqrt(64)

// ---------------------------------------------------------------------------
// Scratch: everything the GEMMs touch lives as pre-split bf16 hi/lo planes.
// ---------------------------------------------------------------------------
__device__ __nv_bfloat16 g_Qh[(size_t)BH * S_LEN * HD];
__device__ __nv_bfloat16 g_Ql[(size_t)BH * S_LEN * HD];
__device__ __nv_bfloat16 g_Kh[(size_t)BH * S_LEN * HD];
__device__ __nv_bfloat16 g_Kl[(size_t)BH * S_LEN * HD];
__device__ __nv_bfloat16 g_Vh[(size_t)BH * S_LEN * HD];
__device__ __nv_bfloat16 g_Vl[(size_t)BH * S_LEN * HD];
__device__ __nv_bfloat16 g_Xh[(size_t)MROWS * DM];
__device__ __nv_bfloat16 g_Xl[(size_t)MROWS * DM];
__device__ __nv_bfloat16 g_Wqh[(size_t)DM * DM];
__device__ __nv_bfloat16 g_Wql[(size_t)DM * DM];
__device__ __nv_bfloat16 g_Wkh[(size_t)DM * DM];
__device__ __nv_bfloat16 g_Wkl[(size_t)DM * DM];
__device__ __nv_bfloat16 g_Wvh[(size_t)DM * DM];
__device__ __nv_bfloat16 g_Wvl[(size_t)DM * DM];
__device__ __nv_bfloat16 g_Woh[(size_t)DM * DM];
__device__ __nv_bfloat16 g_Wol[(size_t)DM * DM];
__device__ __nv_bfloat16 g_Ch[(size_t)MROWS * DM];   // attention context hi
__device__ __nv_bfloat16 g_Cl[(size_t)MROWS * DM];   // attention context lo
__device__ float g_inv[BH * S_LEN];                  // 1/rowsum

// ---------------------------------------------------------------------------
// sm_80-compatible primitives
// ---------------------------------------------------------------------------
__device__ __forceinline__ uint32_t smem_to_u32(const void* p) {
    uint32_t addr;
    asm("{ .reg .u64 tmp; cvta.to.shared.u64 tmp, %1; cvt.u32.u64 %0, tmp; }"
        : "=r"(addr) : "l"(p));
    return addr;
}
__device__ __forceinline__ void ldmx4(uint32_t (&r)[4], uint32_t addr) {
    asm volatile("ldmatrix.sync.aligned.m8n8.x4.shared.b16 {%0,%1,%2,%3}, [%4];"
        : "=r"(r[0]), "=r"(r[1]), "=r"(r[2]), "=r"(r[3]) : "r"(addr));
}
__device__ __forceinline__ void ldmx4t(uint32_t (&r)[4], uint32_t addr) {
    asm volatile("ldmatrix.sync.aligned.m8n8.x4.trans.shared.b16 {%0,%1,%2,%3}, [%4];"
        : "=r"(r[0]), "=r"(r[1]), "=r"(r[2]), "=r"(r[3]) : "r"(addr));
}
__device__ __forceinline__ void mma16816(float (&c)[4],
                                         const uint32_t (&a)[4],
                                         const uint32_t (&b)[2]) {
    asm volatile(
        "mma.sync.aligned.m16n8k16.row.col.f32.bf16.bf16.f32 "
        "{%0,%1,%2,%3}, {%4,%5,%6,%7}, {%8,%9}, {%0,%1,%2,%3};"
        : "+f"(c[0]), "+f"(c[1]), "+f"(c[2]), "+f"(c[3])
        : "r"(a[0]), "r"(a[1]), "r"(a[2]), "r"(a[3]), "r"(b[0]), "r"(b[1]));
}

#define CP16(dst, src) \
    asm volatile("cp.async.cg.shared.global [%0], [%1], 16;" \
        :: "r"((uint32_t)(dst)), "l"((const void*)(src)))
#define CP_COMMIT() asm volatile("cp.async.commit_group;" ::: "memory")
#define CP_WAIT1()  asm volatile("cp.async.wait_group 1;" ::: "memory")
#define CP_WAIT0()  asm volatile("cp.async.wait_group 0;" ::: "memory")

#define SWZ(off) ((off) ^ (((off) >> 3) & 0x70))

// fp32 -> (hi, lo) bf16 split, packed pairwise
__device__ __forceinline__ void split2(float a, float b, uint32_t& wh, uint32_t& wl)
{
    __nv_bfloat16 ha = __float2bfloat16(a), hb = __float2bfloat16(b);
    float ra = a - __bfloat162float(ha);
    float rb = b - __bfloat162float(hb);
    __nv_bfloat16 la = __float2bfloat16(ra), lb = __float2bfloat16(rb);
    wh = (uint32_t)__bfloat16_as_ushort(ha) | ((uint32_t)__bfloat16_as_ushort(hb) << 16);
    wl = (uint32_t)__bfloat16_as_ushort(la) | ((uint32_t)__bfloat16_as_ushort(lb) << 16);
}

// ---------------------------------------------------------------------------
// Prep: split all five fp32 inputs into bf16 hi/lo planes in one launch.
// grid (2048, 5), 256 threads.
// ---------------------------------------------------------------------------
__global__ void split_all(const float* __restrict__ x,
                          const float* __restrict__ Wq,
                          const float* __restrict__ Wk,
                          const float* __restrict__ Wv,
                          const float* __restrict__ Wo)
{
    const float* src;
    uint32_t *dh, *dl;
    int npairs;
    switch (blockIdx.y) {
        case 0:  src = x;  dh = (uint32_t*)g_Xh;  dl = (uint32_t*)g_Xl;  npairs = MROWS * DM / 2; break;
        case 1:  src = Wq; dh = (uint32_t*)g_Wqh; dl = (uint32_t*)g_Wql; npairs = DM * DM / 2; break;
        case 2:  src = Wk; dh = (uint32_t*)g_Wkh; dl = (uint32_t*)g_Wkl; npairs = DM * DM / 2; break;
        case 3:  src = Wv; dh = (uint32_t*)g_Wvh; dl = (uint32_t*)g_Wvl; npairs = DM * DM / 2; break;
        default: src = Wo; dh = (uint32_t*)g_Woh; dl = (uint32_t*)g_Wol; npairs = DM * DM / 2; break;
    }
    int stride = gridDim.x * blockDim.x;
    for (int i = blockIdx.x * blockDim.x + threadIdx.x; i < npairs; i += stride) {
        float2 v = ((const float2*)src)[i];
        uint32_t hw, lw;
        split2(v.x, v.y, hw, lw);
        dh[i] = hw;
        dl[i] = lw;
    }
}

// ---------------------------------------------------------------------------
// HMMA GEMM mainloop, cp.async double-buffered, CTA tile 256m x 128n, BK=64.
// 256 threads = 8 warps, warp tile 64x64 (wm=(wid&3)*64, wn=(wid>>2)*64).
// 3-term products (AhBh + AhBl + AlBh). B fragments via ldmatrix.x4 pairs.
// Stage layout (stride 98304): Ah +0 (32KB), Al +32768, Bh +65536 (16KB), Bl +81920.
// ---------------------------------------------------------------------------
#define GS_AL   32768
#define GS_BH   65536
#define GS_BL   81920
#define GSTAGE  98304
#define GEMM_SMEM_BYTES (2 * GSTAGE)

__device__ __forceinline__ void hmma_mainloop_256x128(
    const __nv_bfloat16* __restrict__ Ah, const __nv_bfloat16* __restrict__ Al,
    const __nv_bfloat16* __restrict__ Bh, const __nv_bfloat16* __restrict__ Bl,
    int m0, int n0, char* sm, float (&acc)[4][8][4])
{
    const int tid  = threadIdx.x;
    const int wid  = tid >> 5;
    const int lane = tid & 31;
    const int wm   = (wid & 3) * 64;
    const int wn   = (wid >> 2) * 64;
    const int lane8 = tid & 7;          // 16B sector within 128B row
    const int rgrp  = tid >> 3;         // base row 0..31

    const uint32_t sbase = smem_to_u32(sm);
    const uint32_t a_rl = (lane & 15);
    const uint32_t a_kb = (lane >> 4) * 16;
    const uint32_t b_row = (lane & 7) + ((lane >> 4) & 1) * 8;   // x4: 2 n-blocks
    const uint32_t b_kb  = ((lane >> 3) & 1) * 16;

    uint32_t ssw[8];
    #pragma unroll
    for (int rr = 0; rr < 8; rr++)
        ssw[rr] = SWZ((uint32_t)(rgrp + rr * 32) * 128 + lane8 * 16);

    // ---- prologue: chunk 0 into stage 0 ----
    {
        const char* pAh = (const char*)(Ah + (size_t)(m0 + rgrp) * DM) + lane8 * 16;
        const char* pAl = (const char*)(Al + (size_t)(m0 + rgrp) * DM) + lane8 * 16;
        const char* pBh = (const char*)(Bh + (size_t)(n0 + rgrp) * DM) + lane8 * 16;
        const char* pBl = (const char*)(Bl + (size_t)(n0 + rgrp) * DM) + lane8 * 16;
        #pragma unroll
        for (int rr = 0; rr < 8; rr++) {
            const size_t g = (size_t)rr * 32 * DM * 2;
            CP16(sbase +         ssw[rr], pAh + g);
            CP16(sbase + GS_AL + ssw[rr], pAl + g);
        }
        #pragma unroll
        for (int rr = 0; rr < 4; rr++) {
            const size_t g = (size_t)rr * 32 * DM * 2;
            CP16(sbase + GS_BH + ssw[rr], pBh + g);
            CP16(sbase + GS_BL + ssw[rr], pBl + g);
        }
        CP_COMMIT();
    }

    for (int kc = 0; kc < 16; kc++) {
        if (kc < 15) {
            const uint32_t sb = sbase + ((kc + 1) & 1) * GSTAGE;
            const size_t goff = (size_t)(kc + 1) * 128;   // bytes into each row
            const char* pAh = (const char*)(Ah + (size_t)(m0 + rgrp) * DM) + goff + lane8 * 16;
            const char* pAl = (const char*)(Al + (size_t)(m0 + rgrp) * DM) + goff + lane8 * 16;
            const char* pBh = (const char*)(Bh + (size_t)(n0 + rgrp) * DM) + goff + lane8 * 16;
            const char* pBl = (const char*)(Bl + (size_t)(n0 + rgrp) * DM) + goff + lane8 * 16;
            #pragma unroll
            for (int rr = 0; rr < 8; rr++) {
                const size_t g = (size_t)rr * 32 * DM * 2;
                CP16(sb +         ssw[rr], pAh + g);
                CP16(sb + GS_AL + ssw[rr], pAl + g);
            }
            #pragma unroll
            for (int rr = 0; rr < 4; rr++) {
                const size_t g = (size_t)rr * 32 * DM * 2;
                CP16(sb + GS_BH + ssw[rr], pBh + g);
                CP16(sb + GS_BL + ssw[rr], pBl + g);
            }
            CP_COMMIT();
            CP_WAIT1();
        } else {
            CP_WAIT0();
        }
        __syncthreads();

        const uint32_t sb = sbase + (kc & 1) * GSTAGE;
        #pragma unroll
        for (int ks = 0; ks < 4; ks++) {
            uint32_t ah[4][4], al[4][4];
            #pragma unroll
            for (int mi = 0; mi < 4; mi++) {
                uint32_t sw = SWZ((uint32_t)(wm + mi * 16 + a_rl) * 128 + ks * 32 + a_kb);
                ldmx4(ah[mi], sb + sw);
                ldmx4(al[mi], sb + GS_AL + sw);
            }
            #pragma unroll
            for (int np = 0; np < 4; np++) {
                uint32_t sw = SWZ((uint32_t)(wn + np * 16 + b_row) * 128 + ks * 32 + b_kb);
                uint32_t b4h[4], b4l[4];
                ldmx4(b4h, sb + GS_BH + sw);
                ldmx4(b4l, sb + GS_BL + sw);
                #pragma unroll
                for (int sub = 0; sub < 2; sub++) {
                    uint32_t bh2[2] = { b4h[sub * 2], b4h[sub * 2 + 1] };
                    uint32_t bl2[2] = { b4l[sub * 2], b4l[sub * 2 + 1] };
                    const int ni = np * 2 + sub;
                    #pragma unroll
                    for (int mi = 0; mi < 4; mi++) {
                        mma16816(acc[mi][ni], ah[mi], bh2);
                        mma16816(acc[mi][ni], ah[mi], bl2);
                        mma16816(acc[mi][ni], al[mi], bh2);
                    }
                }
            }
        }
        __syncthreads();
    }
}

// ---------------------------------------------------------------------------
// QKV projection -> pre-split bf16 hi/lo planes [bh][s][d].
// grid (8 n-tiles, 16 m-tiles, 3), 256 threads, 192KB smem.
// ---------------------------------------------------------------------------
__global__ __launch_bounds__(256, 1)
void qkv_kernel()
{
    extern __shared__ char sm[];
    const __nv_bfloat16* Wh = (blockIdx.z == 0) ? g_Wqh : (blockIdx.z == 1) ? g_Wkh : g_Wvh;
    const __nv_bfloat16* Wl = (blockIdx.z == 0) ? g_Wql : (blockIdx.z == 1) ? g_Wkl : g_Wvl;
    const int m0 = blockIdx.y * 256;
    const int n0 = blockIdx.x * 128;

    float acc[4][8][4];
    #pragma unroll
    for (int i = 0; i < 4; i++)
        #pragma unroll
        for (int j = 0; j < 8; j++)
            #pragma unroll
            for (int r = 0; r < 4; r++) acc[i][j][r] = 0.f;

    hmma_mainloop_256x128(g_Xh, g_Xl, Wh, Wl, m0, n0, sm, acc);

    const int wid  = threadIdx.x >> 5;
    const int lane = threadIdx.x & 31;
    const int wm   = (wid & 3) * 64;
    const int wn   = (wid >> 2) * 64;
    const int gr   = lane >> 2;
    const int gc   = (lane & 3) * 2;

    #pragma unroll
    for (int mi = 0; mi < 4; mi++)
        #pragma unroll
        for (int half = 0; half < 2; half++) {
            int m = m0 + wm + mi * 16 + gr + half * 8;
            int bb = m >> 11, s = m & 2047;
            #pragma unroll
            for (int ni = 0; ni < 8; ni++) {
                int n = n0 + wn + ni * 8 + gc;
                int h = n >> 6, d = n & 63;
                size_t idx = ((size_t)(bb * HEADS + h) * S_LEN + s) * HD + d;
                uint32_t hw, lw;
                split2(acc[mi][ni][half * 2], acc[mi][ni][half * 2 + 1], hw, lw);
                if (blockIdx.z == 0) {
                    *(uint32_t*)(g_Qh + idx) = hw;
                    *(uint32_t*)(g_Ql + idx) = lw;
                } else if (blockIdx.z == 1) {
                    *(uint32_t*)(g_Kh + idx) = hw;
                    *(uint32_t*)(g_Kl + idx) = lw;
                } else {
                    *(uint32_t*)(g_Vh + idx) = hw;
                    *(uint32_t*)(g_Vl + idx) = lw;
                }
            }
        }
}

// ---------------------------------------------------------------------------
// Fused output projection + attnW normalize.
// CTAs [0,128): out = ctx @ Wo^T (16 m-tiles x 8 n-tiles).
// CTAs [128,296): scale attnW rows by g_inv (8-wide float4 ILP, HBM-bound).
// ---------------------------------------------------------------------------
#define NORM_CTAS 168

__global__ __launch_bounds__(256, 1)
void projnorm_kernel(float* __restrict__ Out, float* __restrict__ attnW)
{
    if (blockIdx.x < 128) {
        extern __shared__ char sm[];
        const int m0 = (blockIdx.x >> 3) * 256;
        const int n0 = (blockIdx.x & 7) * 128;

        float acc[4][8][4];
        #pragma unroll
        for (int i = 0; i < 4; i++)
            #pragma unroll
            for (int j = 0; j < 8; j++)
                #pragma unroll
                for (int r = 0; r < 4; r++) acc[i][j][r] = 0.f;

        hmma_mainloop_256x128(g_Ch, g_Cl, g_Woh, g_Wol, m0, n0, sm, acc);

        const int wid  = threadIdx.x >> 5;
        const int lane = threadIdx.x & 31;
        const int wm   = (wid & 3) * 64;
        const int wn   = (wid >> 2) * 64;
        const int gr   = lane >> 2;
        const int gc   = (lane & 3) * 2;

        #pragma unroll
        for (int mi = 0; mi < 4; mi++)
            #pragma unroll
            for (int half = 0; half < 2; half++) {
                int m = m0 + wm + mi * 16 + gr + half * 8;
                float* row = Out + (size_t)m * DM + n0 + wn + gc;
                #pragma unroll
                for (int ni = 0; ni < 8; ni++)
                    *(float2*)(row + ni * 8) = make_float2(acc[mi][ni][half * 2],
                                                           acc[mi][ni][half * 2 + 1]);
            }
    } else {
        // norm: chunks of 8 float4 (128B); 512 float4 per attn row -> chunk
        // never spans rows, so one g_inv lookup per chunk.
        const size_t total_chunks = (size_t)BH * S_LEN * 64;  // 4.19M
        const size_t nthr = (size_t)NORM_CTAS * 256;
        const int nb = blockIdx.x - 128;
        for (size_t c = (size_t)nb * 256 + threadIdx.x; c < total_chunks; c += nthr) {
            size_t base = c * 8;
            float inv = g_inv[base >> 9];
            float4 w[8];
            #pragma unroll
            for (int j = 0; j < 8; j++) w[j] = ((float4*)attnW)[base + j];
            #pragma unroll
            for (int j = 0; j < 8; j++) {
                w[j].x *= inv; w[j].y *= inv; w[j].z *= inv; w[j].w *= inv;
            }
            #pragma unroll
            for (int j = 0; j < 8; j++) ((float4*)attnW)[base + j] = w[j];
        }
    }
}

// ---------------------------------------------------------------------------
// HMMA attention, cp.async double-buffered K/V.
// CTA = 128 queries x one (b,h). 256 threads = 8 warps; warp tile 16q x 128k
// (full key width -> no cross-warp O reduction). K/V B-fragments via x4.
// smem: Q hi/lo 32KB resident; 2 KV stages of 64KB (KH,KL,VH,VL @16KB).
// ---------------------------------------------------------------------------
#define AT_S0   32768
#define KSTAGE  65536
#define AT_SMEM_BYTES (AT_S0 + 2 * KSTAGE)

__global__ __launch_bounds__(256, 1)
void attn_kernel(float* __restrict__ attnW)
{
    extern __shared__ char sm[];
    const int tid  = threadIdx.x;
    const int wid  = tid >> 5;      // 0..7 = q block
    const int lane = tid & 31;
    const int bh   = blockIdx.y;
    const int q0   = blockIdx.x * 128;

    const size_t plane = (size_t)bh * S_LEN * HD;
    const uint32_t sbase = smem_to_u32(sm);

    // load geometry: 4 passes x 32 rows, 16B sectors
    const int l_c16 = tid & 7;
    const int l_row = tid >> 3;     // 0..31
    uint32_t lsw[4];
    #pragma unroll
    for (int p = 0; p < 4; p++)
        lsw[p] = SWZ((uint32_t)((l_row + p * 32) * 128 + l_c16 * 16));

    // ---- Q tile (plain loads, covered by first barrier) ----
    {
        const __nv_bfloat16* qh = g_Qh + plane + (size_t)q0 * HD;
        const __nv_bfloat16* ql = g_Ql + plane + (size_t)q0 * HD;
        #pragma unroll
        for (int p = 0; p < 4; p++) {
            size_t gb = (size_t)(l_row + p * 32) * 64;
            *(uint4*)(sm + lsw[p])         = *(const uint4*)((const char*)(qh + gb) + l_c16 * 16);
            *(uint4*)(sm + 16384 + lsw[p]) = *(const uint4*)((const char*)(ql + gb) + l_c16 * 16);
        }
    }

    // ---- prologue: K/V tile 0 into stage 0 ----
    {
        const uint32_t sb = sbase + AT_S0;
        #pragma unroll
        for (int p = 0; p < 4; p++) {
            size_t gb = (size_t)(l_row + p * 32) * 64;
            CP16(sb +         lsw[p], (const char*)(g_Kh + plane + gb) + l_c16 * 16);
            CP16(sb + 16384 + lsw[p], (const char*)(g_Kl + plane + gb) + l_c16 * 16);
            CP16(sb + 32768 + lsw[p], (const char*)(g_Vh + plane + gb) + l_c16 * 16);
            CP16(sb + 49152 + lsw[p], (const char*)(g_Vl + plane + gb) + l_c16 * 16);
        }
        CP_COMMIT();
    }

    const uint32_t a_rl  = (lane & 15);
    const uint32_t a_kb  = (lane >> 4) * 16;
    const uint32_t b_row = (lane & 7) + ((lane >> 4) & 1) * 8;   // K x4 (2 n-blocks)
    const uint32_t b_kb  = ((lane >> 3) & 1) * 16;
    const uint32_t v_row = (lane & 7) + ((lane >> 3) & 1) * 8;   // V x4.trans
    const uint32_t v_cb  = ((lane >> 4) & 1) * 16;

    float Oacc[8][4];
    #pragma unroll
    for (int i = 0; i < 8; i++)
        #pragma unroll
        for (int j = 0; j < 4; j++) Oacc[i][j] = 0.f;
    float rs0 = 0.f, rs1 = 0.f;

    for (int kt = 0; kt < 16; kt++) {
        if (kt < 15) {
            const size_t goff = (size_t)(kt + 1) * 128 * HD;
            const uint32_t sb = sbase + AT_S0 + ((kt + 1) & 1) * KSTAGE;
            #pragma unroll
            for (int p = 0; p < 4; p++) {
                size_t gb = goff + (size_t)(l_row + p * 32) * 64;
                CP16(sb +         lsw[p], (const char*)(g_Kh + plane + gb) + l_c16 * 16);
                CP16(sb + 16384 + lsw[p], (const char*)(g_Kl + plane + gb) + l_c16 * 16);
                CP16(sb + 32768 + lsw[p], (const char*)(g_Vh + plane + gb) + l_c16 * 16);
                CP16(sb + 49152 + lsw[p], (const char*)(g_Vl + plane + gb) + l_c16 * 16);
            }
            CP_COMMIT();
            CP_WAIT1();
        } else {
            CP_WAIT0();
        }
        __syncthreads();

        const uint32_t kvb = AT_S0 + (kt & 1) * KSTAGE;

        // ---- S = Q K^T (warp: 16q x 128k), 3-MMA split ----
        float Sacc[16][4];
        #pragma unroll
        for (int i = 0; i < 16; i++)
            #pragma unroll
            for (int j = 0; j < 4; j++) Sacc[i][j] = 0.f;

        #pragma unroll
        for (int ks = 0; ks < 4; ks++) {
            uint32_t ah[4], al[4];
            uint32_t qa = SWZ((uint32_t)(wid * 16 + a_rl) * 128 + ks * 32 + a_kb);
            ldmx4(ah, sbase + qa);
            ldmx4(al, sbase + 16384 + qa);
            #pragma unroll
            for (int np = 0; np < 8; np++) {
                uint32_t ka = SWZ((uint32_t)(np * 16 + b_row) * 128 + ks * 32 + b_kb);
                uint32_t k4h[4], k4l[4];
                ldmx4(k4h, sbase + kvb + ka);
                ldmx4(k4l, sbase + kvb + 16384 + ka);
                #pragma unroll
                for (int sub = 0; sub < 2; sub++) {
                    uint32_t bh2[2] = { k4h[sub * 2], k4h[sub * 2 + 1] };
                    uint32_t bl2[2] = { k4l[sub * 2], k4l[sub * 2 + 1] };
                    const int ni = np * 2 + sub;
                    mma16816(Sacc[ni], ah, bh2);
                    mma16816(Sacc[ni], ah, bl2);
                    mma16816(Sacc[ni], al, bh2);
                }
            }
        }

        // ---- exp + attnW store + rowsum + repack to A-fragments ----
        uint32_t pah[8][4], pal[8][4];
        float* Wrow = attnW + ((size_t)bh * S_LEN + q0 + wid * 16 + (lane >> 2)) * S_LEN
                    + kt * 128 + (lane & 3) * 2;
        #pragma unroll
        for (int ni = 0; ni < 16; ni++) {
            float e0 = __expf(Sacc[ni][0] * SCALE);
            float e1 = __expf(Sacc[ni][1] * SCALE);
            float e2 = __expf(Sacc[ni][2] * SCALE);
            float e3 = __expf(Sacc[ni][3] * SCALE);
            rs0 += e0 + e1;
            rs1 += e2 + e3;
            *(float2*)(Wrow + ni * 8)                     = make_float2(e0, e1);
            *(float2*)(Wrow + (size_t)8 * S_LEN + ni * 8) = make_float2(e2, e3);
            uint32_t h01, l01, h23, l23;
            split2(e0, e1, h01, l01);
            split2(e2, e3, h23, l23);
            int kp = ni >> 1, o = (ni & 1) * 2;
            pah[kp][o] = h01; pah[kp][o + 1] = h23;
            pal[kp][o] = l01; pal[kp][o + 1] = l23;
        }

        // ---- O += P @ V (warp: 16q x 64d over full 128 keys) ----
        #pragma unroll
        for (int kp = 0; kp < 8; kp++) {
            #pragma unroll
            for (int ndp = 0; ndp < 4; ndp++) {
                uint32_t va = SWZ((uint32_t)(kp * 16 + v_row) * 128 + ndp * 32 + v_cb);
                uint32_t v4h[4], v4l[4];
                ldmx4t(v4h, sbase + kvb + 32768 + va);
                ldmx4t(v4l, sbase + kvb + 49152 + va);
                #pragma unroll
                for (int sub = 0; sub < 2; sub++) {
                    uint32_t bh2[2] = { v4h[sub * 2], v4h[sub * 2 + 1] };
                    uint32_t bl2[2] = { v4l[sub * 2], v4l[sub * 2 + 1] };
                    const int nd = ndp * 2 + sub;
                    mma16816(Oacc[nd], pah[kp], bh2);
                    mma16816(Oacc[nd], pal[kp], bh2);
                    mma16816(Oacc[nd], pah[kp], bl2);
                }
            }
        }
        __syncthreads();
    }

    // ---- epilogue: per-warp rowsums, normalize, store split ctx ----
    rs0 += __shfl_xor_sync(0xffffffffu, rs0, 1);
    rs0 += __shfl_xor_sync(0xffffffffu, rs0, 2);
    rs1 += __shfl_xor_sync(0xffffffffu, rs1, 1);
    rs1 += __shfl_xor_sync(0xffffffffu, rs1, 2);
    float inv0 = 1.f / rs0;
    float inv1 = 1.f / rs1;

    const int b = bh >> 4, h = bh & 15;
    const int r0 = wid * 16 + (lane >> 2);
    const int r1 = r0 + 8;
    size_t i0 = ((size_t)b * S_LEN + q0 + r0) * DM + h * 64 + (lane & 3) * 2;
    size_t i1 = ((size_t)b * S_LEN + q0 + r1) * DM + h * 64 + (lane & 3) * 2;
    #pragma unroll
    for (int nd = 0; nd < 8; nd++) {
        uint32_t hw, lw;
        split2(Oacc[nd][0] * inv0, Oacc[nd][1] * inv0, hw, lw);
        *(uint32_t*)(g_Ch + i0 + nd * 8) = hw;
        *(uint32_t*)(g_Cl + i0 + nd * 8) = lw;
        split2(Oacc[nd][2] * inv1, Oacc[nd][3] * inv1, hw, lw);
        *(uint32_t*)(g_Ch + i1 + nd * 8) = hw;
        *(uint32_t*)(g_Cl + i1 + nd * 8) = lw;
    }
    if ((lane & 3) == 0) {
        g_inv[bh * S_LEN + q0 + r0] = inv0;
        g_inv[bh * S_LEN + q0 + r1] = inv1;
    }
}

// ---------------------------------------------------------------------------
// Launcher
// ---------------------------------------------------------------------------
extern "C" void kernel_launch(void* const* d_in, const int* in_sizes, int n_in,
                              void* d_out, int out_size)
{
    const float* x  = (const float*)d_in[0];
    const float* Wq = (const float*)d_in[1];
    const float* Wk = (const float*)d_in[2];
    const float* Wv = (const float*)d_in[3];
    const float* Wo = (const float*)d_in[4];

    float* out   = (float*)d_out;
    float* attnW = out + (size_t)MROWS * DM;

    cudaFuncSetAttribute(qkv_kernel,
                         cudaFuncAttributeMaxDynamicSharedMemorySize, GEMM_SMEM_BYTES);
    cudaFuncSetAttribute(projnorm_kernel,
                         cudaFuncAttributeMaxDynamicSharedMemorySize, GEMM_SMEM_BYTES);
    cudaFuncSetAttribute(attn_kernel,
                         cudaFuncAttributeMaxDynamicSharedMemorySize, AT_SMEM_BYTES);

    dim3 gs(2048, 5);
    split_all<<<gs, 256>>>(x, Wq, Wk, Wv, Wo);

    dim3 gq(DM / 128, MROWS / 256, 3);
    qkv_kernel<<<gq, 256, GEMM_SMEM_BYTES>>>();

    dim3 ga(S_LEN / 128, BH);
    attn_kernel<<<ga, 256, AT_SMEM_BYTES>>>(attnW);

    projnorm_kernel<<<128 + NORM_CTAS, 256, GEMM_SMEM_BYTES>>>(out, attnW);
}